// round 10
// baseline (speedup 1.0000x reference)
#include <cuda_runtime.h>

#define NN   8192
#define NE   131072
#define NB   256
#define NHF  128
#define FIN  64
#define H3   384
#define D6   768
#define D12  1536
#define G4   3072
#define NBLK 512
#define NTHR 256

// ---------------- scratch ----------------
__device__ __align__(16) float g_h[2][NN * H3];
__device__ __align__(16) float g_x[2][NN * D6];
__device__ __align__(16) float g_xw[2][NN * NHF];
__device__ float g_deg[2][NN];
__device__ int   g_cnt[2][NN];
__device__ int   g_cursor[2][NN];
__device__ int   g_rowptr[2][NN + 1];
__device__ int   g_csrc[2][NE];
__device__ float g_cnrm[2][NE];
__device__ float g_dinv[2][NN];
__device__ int   g_starts[2][NB + 1];
__device__ float g_cvec[G4];
__device__ __align__(16) float g_rb[2][NB * D6];
__device__ __align__(16) float g_gates[2][NB * G4];
__device__ __align__(16) float g_z[NB * G4];
__device__ __align__(16) float g_z1pre[NB * 256];
__device__ unsigned g_barc = 0;
__device__ unsigned g_barg = 0;

union SMem {
    struct { float As[16][64]; float Bs[16][68]; } g;        // 8448 B (GEMM tiles)
    struct { float hq[D6]; float sc[512]; float red[256]; } a; // 6144 B (attn / cvec / mlp)
};

__device__ __forceinline__ float wredsum(float v) {
#pragma unroll
    for (int o = 16; o; o >>= 1) v += __shfl_xor_sync(0xffffffffu, v, o);
    return v;
}
__device__ __forceinline__ float sgm(float x) { return 1.f / (1.f + expf(-x)); }

// software grid barrier: all NBLK blocks are co-resident (launch_bounds guarantees 4/SM)
__device__ __forceinline__ void gridbar() {
    __syncthreads();
    if (threadIdx.x == 0) {
        unsigned old = atomicAdd(&g_barg, 0u);
        __threadfence();
        if (atomicInc(&g_barc, NBLK - 1u) == NBLK - 1u) {
            __threadfence();
            atomicExch(&g_barg, old + 1u);   // release (counter auto-wrapped to 0)
        } else {
            while (atomicAdd(&g_barg, 0u) == old) __nanosleep(32);
        }
        __threadfence();
    }
    __syncthreads();
}

// ---------------- GEMM tile bodies (proven 64x64, 4x4, LDS.128) ----------------
__device__ __forceinline__ void gemm_xw_tile(SMem& sm, const float* __restrict__ X, int ldx,
                                             int K, const float* __restrict__ W,
                                             int col, int row, int g) {
    int tid = threadIdx.x, tx = tid & 15, ty = tid >> 4;
    int colBase = col * 64, rowBase = row * 64;
    float acc[4][4] = {};
    for (int k0 = 0; k0 < K; k0 += 16) {
        __syncthreads();
#pragma unroll
        for (int l = 0; l < 4; l++) {
            int idx = tid + l * 256;
            int m = idx >> 4, kk = idx & 15;
            sm.g.As[kk][m] = X[(size_t)(rowBase + m) * ldx + k0 + kk];
            sm.g.Bs[kk][m] = W[(size_t)(k0 + kk) * NHF + colBase + m];
        }
        __syncthreads();
#pragma unroll
        for (int kk = 0; kk < 16; kk++) {
            float4 a4 = *(const float4*)&sm.g.As[kk][ty * 4];
            float4 b4 = *(const float4*)&sm.g.Bs[kk][tx * 4];
            float av[4] = { a4.x, a4.y, a4.z, a4.w };
            float bv[4] = { b4.x, b4.y, b4.z, b4.w };
#pragma unroll
            for (int i = 0; i < 4; i++)
#pragma unroll
                for (int j = 0; j < 4; j++) acc[i][j] += av[i] * bv[j];
        }
    }
#pragma unroll
    for (int i = 0; i < 4; i++)
#pragma unroll
        for (int j = 0; j < 4; j++)
            g_xw[g][(size_t)(rowBase + ty * 4 + i) * NHF + colBase + tx * 4 + j] = acc[i][j];
}

__device__ __forceinline__ void gates_tile(SMem& sm, int g, int col, int row,
                                           const float* __restrict__ Wih) {
    int tid = threadIdx.x, tx = tid & 15, ty = tid >> 4;
    int colBase = col * 64, rowBase = row * 64;
    const float* A = g_rb[g];
    const float* B = Wih + D6;
    float acc[4][4] = {};
    for (int k0 = 0; k0 < D6; k0 += 16) {
        __syncthreads();
#pragma unroll
        for (int l = 0; l < 4; l++) {
            int idx = tid + l * 256;
            int m = idx >> 4, kk = idx & 15;
            sm.g.As[kk][m] = A[(size_t)(rowBase + m) * D6 + k0 + kk];
            sm.g.Bs[kk][m] = B[(size_t)(colBase + m) * D12 + k0 + kk];
        }
        __syncthreads();
#pragma unroll
        for (int kk = 0; kk < 16; kk++) {
            float4 a4 = *(const float4*)&sm.g.As[kk][ty * 4];
            float4 b4 = *(const float4*)&sm.g.Bs[kk][tx * 4];
            float av[4] = { a4.x, a4.y, a4.z, a4.w };
            float bv[4] = { b4.x, b4.y, b4.z, b4.w };
#pragma unroll
            for (int i = 0; i < 4; i++)
#pragma unroll
                for (int j = 0; j < 4; j++) acc[i][j] += av[i] * bv[j];
        }
    }
#pragma unroll
    for (int i = 0; i < 4; i++) {
        int r = rowBase + ty * 4 + i;
#pragma unroll
        for (int j = 0; j < 4; j++) {
            int c = colBase + tx * 4 + j;
            g_gates[g][(size_t)r * G4 + c] = acc[i][j] + g_cvec[c];
        }
    }
}

__device__ __forceinline__ void mlp1_tile(SMem& sm, int col, int row, int kz,
                                          const float* __restrict__ Wp1) {
    int tid = threadIdx.x, tx = tid & 15, ty = tid >> 4;
    int colBase = col * 64, rowBase = row * 64, kBase = kz * 128;
    float acc[4][4] = {};
    for (int k0 = 0; k0 < 128; k0 += 16) {
        __syncthreads();
#pragma unroll
        for (int l = 0; l < 4; l++) {
            int idx = tid + l * 256;
            int m = idx >> 4, kk = idx & 15;
            sm.g.As[kk][m] = g_z[(size_t)(rowBase + m) * G4 + kBase + k0 + kk];
            sm.g.Bs[kk][m] = Wp1[(size_t)(colBase + m) * G4 + kBase + k0 + kk];
        }
        __syncthreads();
#pragma unroll
        for (int kk = 0; kk < 16; kk++) {
            float4 a4 = *(const float4*)&sm.g.As[kk][ty * 4];
            float4 b4 = *(const float4*)&sm.g.Bs[kk][tx * 4];
            float av[4] = { a4.x, a4.y, a4.z, a4.w };
            float bv[4] = { b4.x, b4.y, b4.z, b4.w };
#pragma unroll
            for (int i = 0; i < 4; i++)
#pragma unroll
                for (int j = 0; j < 4; j++) acc[i][j] += av[i] * bv[j];
        }
    }
#pragma unroll
    for (int i = 0; i < 4; i++)
#pragma unroll
        for (int j = 0; j < 4; j++)
            atomicAdd(&g_z1pre[(size_t)(rowBase + ty * 4 + i) * 256 + colBase + tx * 4 + j],
                      acc[i][j]);
}

// ---------------- gather stage (proven warp-per-node float4; l2 fused for last layer) ----------------
template<bool FUSE_L2>
__device__ __forceinline__ void stage_gather(int off, const float* __restrict__ bias) {
    int lane = threadIdx.x & 31, w = threadIdx.x >> 5;
    for (int t = blockIdx.x * 8 + w; t < 2 * NN; t += NBLK * 8) {
        int g = t >> 13, n = t & (NN - 1);
        const float4* xw4 = (const float4*)g_xw[g];
        float di = g_dinv[g][n];
        float sn = di * di;
        float4 bb = ((const float4*)bias)[lane];
        float4 sv = xw4[(size_t)n * 32 + lane];
        float ax = bb.x + sn * sv.x, ay = bb.y + sn * sv.y;
        float az = bb.z + sn * sv.z, aw = bb.w + sn * sv.w;
        int e0 = g_rowptr[g][n], e1 = g_rowptr[g][n + 1];
        const int* __restrict__ csrc = g_csrc[g];
        const float* __restrict__ cnrm = g_cnrm[g];
        for (int e = e0; e < e1; e++) {
            int s = csrc[e];
            float nm = cnrm[e];
            float4 v = xw4[(size_t)s * 32 + lane];
            ax += nm * v.x; ay += nm * v.y; az += nm * v.z; aw += nm * v.w;
        }
        ax = (ax >= 0.f) ? ax : 0.2f * ax;
        ay = (ay >= 0.f) ? ay : 0.2f * ay;
        az = (az >= 0.f) ? az : 0.2f * az;
        aw = (aw >= 0.f) ? aw : 0.2f * aw;
        if (!FUSE_L2) {
            float4* o = (float4*)(g_h[g] + (size_t)n * H3 + off);
            o[lane] = make_float4(ax, ay, az, aw);
        } else {
            // fused L2 normalization: cols 0..255 from g_h (written in prior stages), cols 256..383 in regs
            const float4* hrow = (const float4*)(g_h[g] + (size_t)n * H3);
            float4 v0 = hrow[lane];
            float4 v1 = hrow[lane + 32];
            float ss = v0.x * v0.x + v0.y * v0.y + v0.z * v0.z + v0.w * v0.w
                     + v1.x * v1.x + v1.y * v1.y + v1.z * v1.z + v1.w * v1.w
                     + ax * ax + ay * ay + az * az + aw * aw;
            ss = wredsum(ss);
            float inv = 1.f / fmaxf(sqrtf(ss), 1e-12f);
            float4* xr = (float4*)(g_x[g] + (size_t)n * D6);
            xr[lane]      = make_float4(v0.x * inv, v0.y * inv, v0.z * inv, v0.w * inv);
            xr[lane + 32] = make_float4(v1.x * inv, v1.y * inv, v1.z * inv, v1.w * inv);
            xr[lane + 64] = make_float4(ax * inv, ay * inv, az * inv, aw * inv);
        }
    }
}

// ---------------- attention bodies (proven) ----------------
__device__ __forceinline__ void attn_core(SMem& sm, int g, int b, float* rout) {
    int tid = threadIdx.x, lane = tid & 31, w = tid >> 5;
    int s = g_starts[g][b], e = g_starts[g][b + 1], cnt = e - s;
    if (cnt <= 0) {
        for (int j = tid; j < D6; j += NTHR) rout[j] = 0.f;
        return;
    }
    const float* x = g_x[g];
    for (int t = w; t < cnt; t += 8) {
        const float* xr = x + (size_t)(s + t) * D6;
        float p = 0.f;
#pragma unroll
        for (int q = 0; q < 24; q++) p += xr[lane + 32 * q] * sm.a.hq[lane + 32 * q];
        p = wredsum(p);
        if (lane == 0) sm.a.sc[t] = p;
    }
    __syncthreads();
    float lm = -3.4e38f;
    for (int t = tid; t < cnt; t += NTHR) lm = fmaxf(lm, sm.a.sc[t]);
    sm.a.red[tid] = lm; __syncthreads();
    for (int o = 128; o > 0; o >>= 1) { if (tid < o) sm.a.red[tid] = fmaxf(sm.a.red[tid], sm.a.red[tid + o]); __syncthreads(); }
    float m = sm.a.red[0]; __syncthreads();
    float ls = 0.f;
    for (int t = tid; t < cnt; t += NTHR) { float ev = expf(sm.a.sc[t] - m); sm.a.sc[t] = ev; ls += ev; }
    sm.a.red[tid] = ls; __syncthreads();
    for (int o = 128; o > 0; o >>= 1) { if (tid < o) sm.a.red[tid] += sm.a.red[tid + o]; __syncthreads(); }
    float inv = 1.f / sm.a.red[0]; __syncthreads();
    float a0 = 0.f, a1 = 0.f, a2 = 0.f;
    for (int t = 0; t < cnt; t++) {
        float wv = sm.a.sc[t];
        const float* xr = x + (size_t)(s + t) * D6;
        a0 += wv * xr[tid];
        a1 += wv * xr[tid + 256];
        a2 += wv * xr[tid + 512];
    }
    rout[tid] = a0 * inv;
    rout[tid + 256] = a1 * inv;
    rout[tid + 512] = a2 * inv;
}

// ---------------- the mega kernel ----------------
__global__ void __launch_bounds__(NTHR, 4) k_mega(
    const float* __restrict__ f1, const float* __restrict__ f2,
    const float* __restrict__ ea1, const float* __restrict__ ea2,
    const float* __restrict__ W0, const float* __restrict__ bW0,
    const float* __restrict__ W1, const float* __restrict__ bW1,
    const float* __restrict__ W2, const float* __restrict__ bW2,
    const float* __restrict__ Wih, const float* __restrict__ bih,
    const float* __restrict__ Whh, const float* __restrict__ bhh,
    const float* __restrict__ Wp1, const float* __restrict__ bp1,
    const float* __restrict__ Wp2, const float* __restrict__ bp2,
    const float* __restrict__ Wp3, const float* __restrict__ bp3,
    const int* __restrict__ ei1, const int* __restrict__ ei2,
    const int* __restrict__ b1, const int* __restrict__ b2,
    float* __restrict__ out)
{
    __shared__ SMem sm;
    __shared__ int s_wsum[8];
    int tid = threadIdx.x, lane = tid & 31, w = tid >> 5;
    int bid = blockIdx.x;

    // ===== S0: zero cnt/deg + zero z1pre + cvec =====
    for (int i = bid * NTHR + tid; i < 2 * NN; i += NBLK * NTHR) {
        int g = i >> 13, n = i & (NN - 1);
        g_cnt[g][n] = 0;
        g_deg[g][n] = 0.f;
    }
    if (bid < 256) g_z1pre[(size_t)bid * 256 + tid] = 0.f;
    for (int j = tid; j < D6; j += NTHR) {
        float gi = bih[j] + bhh[j];
        float gg = bih[2 * D6 + j] + bhh[2 * D6 + j];
        float go = bih[3 * D6 + j] + bhh[3 * D6 + j];
        float c = sgm(gi) * tanhf(gg);
        sm.a.hq[j] = sgm(go) * tanhf(c);     // hv
    }
    __syncthreads();
    {
        int gout = bid * 8 + w;
        if (gout < G4) {
            const float* wi = Wih + (size_t)gout * D12;
            const float* wh = Whh + (size_t)gout * D6;
            float p = 0.f;
#pragma unroll
            for (int t = 0; t < 24; t++) {
                int k = lane + 32 * t;
                p += sm.a.hq[k] * (wi[k] + wh[k]);
            }
            p = wredsum(p);
            if (lane == 0) g_cvec[gout] = bih[gout] + bhh[gout] + p;
        }
    }
    gridbar();

    // ===== S1: count (degrees + per-node edge counts) =====
    for (int i = bid * NTHR + tid; i < 2 * NE; i += NBLK * NTHR) {
        int g = i >= NE;
        int e = g ? i - NE : i;
        const int* ei = g ? ei2 : ei1;
        const float* ew = g ? ea2 : ea1;
        int d = ei[NE + e];
        atomicAdd(&g_cnt[g][d], 1);
        atomicAdd(&g_deg[g][d], ew[e]);
    }
    gridbar();

    // ===== S2: scan (blocks 0-1) + dinv/starts + gemm0 =====
    if (bid < 2) {
        int g = bid;
        int b0 = tid * 32;
        int s = 0;
        for (int i = 0; i < 32; i++) s += g_cnt[g][b0 + i];
        int x = s;
#pragma unroll
        for (int o = 1; o < 32; o <<= 1) {
            int y = __shfl_up_sync(0xffffffffu, x, o);
            if (lane >= o) x += y;
        }
        if (lane == 31) s_wsum[w] = x;
        __syncthreads();
        int woff = 0;
        for (int k = 0; k < w; k++) woff += s_wsum[k];
        int run = woff + x - s;
        for (int i = 0; i < 32; i++) {
            int c = g_cnt[g][b0 + i];
            g_rowptr[g][b0 + i] = run;
            g_cursor[g][b0 + i] = run;
            run += c;
        }
        if (tid == NTHR - 1) g_rowptr[g][NN] = run;
        __syncthreads();
    }
    for (int i = bid * NTHR + tid; i < 2 * NN; i += NBLK * NTHR) {
        int g = i >> 13, n = i & (NN - 1);
        g_dinv[g][n] = rsqrtf(g_deg[g][n] + 1.0f);
        const int* batch = g ? b2 : b1;
        int b = batch[n];
        if (n == 0) {
            for (int bb = 0; bb <= b; bb++) g_starts[g][bb] = 0;
        } else {
            int pb = batch[n - 1];
            if (pb != b) for (int bb = pb + 1; bb <= b; bb++) g_starts[g][bb] = n;
        }
        if (n == NN - 1) for (int bb = b + 1; bb <= NB; bb++) g_starts[g][bb] = NN;
    }
    {   // gemm0: 512 tiles, one per block
        int col = bid & 1, row = (bid >> 1) & 127, g = bid >> 8;
        gemm_xw_tile(sm, g ? f2 : f1, FIN, FIN, W0, col, row, g);
    }
    gridbar();

    // ===== S3: fill CSR =====
    for (int i = bid * NTHR + tid; i < 2 * NE; i += NBLK * NTHR) {
        int g = i >= NE;
        int e = g ? i - NE : i;
        const int* ei = g ? ei2 : ei1;
        const float* ew = g ? ea2 : ea1;
        int s = ei[e], d = ei[NE + e];
        int pos = atomicAdd(&g_cursor[g][d], 1);
        g_csrc[g][pos] = s;
        g_cnrm[g][pos] = g_dinv[g][s] * ew[e] * g_dinv[g][d];
    }
    gridbar();

    // ===== S4: gather layer 0 =====
    stage_gather<false>(0, bW0);
    gridbar();

    // ===== S5: gemm layer 1 =====
    {
        int col = bid & 1, row = (bid >> 1) & 127, g = bid >> 8;
        gemm_xw_tile(sm, g_h[g], H3, NHF, W1, col, row, g);
    }
    gridbar();

    // ===== S6: gather layer 1 =====
    stage_gather<false>(NHF, bW1);
    gridbar();

    // ===== S7: gemm layer 2 =====
    {
        int col = bid & 1, row = (bid >> 1) & 127, g = bid >> 8;
        gemm_xw_tile(sm, g_h[g] + NHF, H3, NHF, W2, col, row, g);
    }
    gridbar();

    // ===== S8: gather layer 2 + fused L2 normalize -> g_x =====
    stage_gather<true>(2 * NHF, bW2);
    gridbar();

    // ===== S9: block-diagonal interaction (one batch per block; blocks >= NB idle) =====
    for (int b = bid; b < NB; b += NBLK) {
        int s1 = g_starts[0][b], e1 = g_starts[0][b + 1];
        int s2 = g_starts[1][b], e2 = g_starts[1][b + 1];
        int n1 = e1 - s1, n2 = e2 - s2, tot = n1 + n2;
        for (int t = w; t < tot; t += 8) {
            const float *src, *oth;
            float* outp;
            int row, obase, ocnt;
            if (t < n1) { row = s1 + t;        src = g_x[0]; oth = g_x[1]; obase = s2; ocnt = n2; outp = g_x[0]; }
            else        { row = s2 + (t - n1); src = g_x[1]; oth = g_x[0]; obase = s1; ocnt = n1; outp = g_x[1]; }
            const float* sr = src + (size_t)row * D6;
            float svv[12], acc[12];
#pragma unroll
            for (int q = 0; q < 12; q++) { svv[q] = sr[lane + 32 * q]; acc[q] = 0.f; }
            for (int jj = 0; jj < ocnt; jj++) {
                const float* vr = oth + (size_t)(obase + jj) * D6;
                float vv[12], p = 0.f;
#pragma unroll
                for (int q = 0; q < 12; q++) { vv[q] = vr[lane + 32 * q]; p += svv[q] * vv[q]; }
                p = wredsum(p);
#pragma unroll
                for (int q = 0; q < 12; q++) acc[q] += p * vv[q];
            }
            float* orow = outp + (size_t)row * D6 + H3;
#pragma unroll
            for (int q = 0; q < 12; q++) orow[lane + 32 * q] = acc[q];
        }
    }
    gridbar();

    // ===== S10: attn step 1 (h from biases) -> rb =====
    {
        int task = bid;            // 512 tasks, one per block
        int g = task >= NB, b = task & (NB - 1);
        for (int j = tid; j < D6; j += NTHR) {
            float gi = bih[j] + bhh[j];
            float gg = bih[2 * D6 + j] + bhh[2 * D6 + j];
            float go = bih[3 * D6 + j] + bhh[3 * D6 + j];
            float c = sgm(gi) * tanhf(gg);
            sm.a.hq[j] = sgm(go) * tanhf(c);
        }
        __syncthreads();
        attn_core(sm, g, b, g_rb[g] + (size_t)b * D6);
    }
    gridbar();

    // ===== S11: gates2 GEMM (384 tiles) =====
    for (int t = bid; t < 384; t += NBLK) {
        int col = t % 48, row = (t / 48) & 3, g = t / 192;
        gates_tile(sm, g, col, row, Wih);
    }
    gridbar();

    // ===== S12: attn step 2 (lstm2 + attention) -> z =====
    {
        int task = bid;
        int g = task >= NB, b = task & (NB - 1);
        const float* gt = g_gates[g] + (size_t)b * G4;
        float* zb = g_z + (size_t)b * G4 + (g ? D12 : 0);
        for (int j = tid; j < D6; j += NTHR) {
            float gi1 = bih[j] + bhh[j];
            float gg1 = bih[2 * D6 + j] + bhh[2 * D6 + j];
            float cv = sgm(gi1) * tanhf(gg1);
            float gi = gt[j], gf = gt[D6 + j], gg = gt[2 * D6 + j], go = gt[3 * D6 + j];
            float c = sgm(gf) * cv + sgm(gi) * tanhf(gg);
            float h = sgm(go) * tanhf(c);
            sm.a.hq[j] = h;
            zb[j] = h;
        }
        __syncthreads();
        attn_core(sm, g, b, zb + D6);
    }
    gridbar();

    // ===== S13: mlp1 split-K GEMM (384 tiles, atomic accumulate) =====
    for (int t = bid; t < 384; t += NBLK) {
        int col = t & 3, row = (t >> 2) & 3, kz = t >> 4;
        mlp1_tile(sm, col, row, kz, Wp1);
    }
    gridbar();

    // ===== S14: mlp tail (relu -> fc2 -> relu -> fc3 -> sigmoid), one block per batch =====
    if (bid < NB) {
        int b = bid;
        float* zs = sm.a.sc;          // 256 floats
        float* z2s = sm.a.red;        // 128 floats used
        zs[tid] = fmaxf(g_z1pre[(size_t)b * 256 + tid] + bp1[tid], 0.f);
        __syncthreads();
#pragma unroll
        for (int oo = 0; oo < 16; oo++) {
            int o = w * 16 + oo;
            const float* wr = Wp2 + (size_t)o * 256;
            float p = 0.f;
#pragma unroll
            for (int k = 0; k < 8; k++) p += zs[lane + 32 * k] * wr[lane + 32 * k];
            p = wredsum(p);
            if (lane == 0) z2s[o] = fmaxf(p + bp2[o], 0.f);
        }
        __syncthreads();
        if (w == 0) {
            float p = 0.f;
#pragma unroll
            for (int k = 0; k < 4; k++) p += z2s[lane + 32 * k] * Wp3[lane + 32 * k];
            p = wredsum(p);
            if (lane == 0) out[b] = 1.f / (1.f + expf(-p - bp3[0]));
        }
    }
}

// ---------------- launch: ONE kernel ----------------
extern "C" void kernel_launch(void* const* d_in, const int* in_sizes, int n_in,
                              void* d_out, int out_size) {
    k_mega<<<NBLK, NTHR>>>(
        (const float*)d_in[0], (const float*)d_in[1],
        (const float*)d_in[2], (const float*)d_in[3],
        (const float*)d_in[4], (const float*)d_in[5],
        (const float*)d_in[6], (const float*)d_in[7],
        (const float*)d_in[8], (const float*)d_in[9],
        (const float*)d_in[10], (const float*)d_in[11],
        (const float*)d_in[12], (const float*)d_in[13],
        (const float*)d_in[14], (const float*)d_in[15],
        (const float*)d_in[16], (const float*)d_in[17],
        (const float*)d_in[18], (const float*)d_in[19],
        (const int*)d_in[20], (const int*)d_in[21],
        (const int*)d_in[22], (const int*)d_in[23],
        (float*)d_out);
}

// round 11
// speedup vs baseline: 1.1293x; 1.1293x over previous
#include <cuda_runtime.h>

#define NN   8192
#define NE   131072
#define NB   256
#define NHF  128
#define FIN  64
#define H3   384
#define D6   768
#define D12  1536
#define G4   3072
#define NBLK 512
#define NTHR 256

// ---------------- scratch ----------------
__device__ __align__(16) float g_h[2][NN * H3];
__device__ __align__(16) float g_x[2][NN * D6];
__device__ __align__(16) float g_xw[2][NN * NHF];
__device__ float g_deg[2][NN];
__device__ int   g_cnt[2][NN];
__device__ int   g_cursor[2][NN];
__device__ int   g_rowptr[2][NN + 1];
__device__ int   g_csrc[2][NE];
__device__ float g_cnrm[2][NE];
__device__ float g_dinv[2][NN];
__device__ int   g_starts[2][NB + 1];
__device__ float g_cvec[G4];
__device__ __align__(16) float g_rb[2][NB * D6];
__device__ __align__(16) float g_gates[2][NB * G4];
__device__ __align__(16) float g_z[NB * G4];
__device__ __align__(16) float g_z1pre[NB * 256];
__device__ unsigned g_barc = 0;
__device__ volatile unsigned g_barg = 0;

union SMem {
    struct { float As[16][64]; float Bs[16][68]; } g;          // 8448 B (GEMM tiles)
    struct { float hq[D6]; float sc[512]; float red[256]; } a; // 6144 B (attn / cvec / mlp)
};

__device__ __forceinline__ float wredsum(float v) {
#pragma unroll
    for (int o = 16; o; o >>= 1) v += __shfl_xor_sync(0xffffffffu, v, o);
    return v;
}
__device__ __forceinline__ float sgm(float x) { return 1.f / (1.f + expf(-x)); }

// software grid barrier: arrival = one atomicInc per block; POLLING = plain volatile
// loads (no RMW — R10's atomicAdd(...,0) poll serialized 512 blocks at the L2 atomic ALU)
__device__ __forceinline__ void gridbar() {
    __syncthreads();
    if (threadIdx.x == 0) {
        __threadfence();
        unsigned old = g_barg;                        // volatile read (all blocks agree)
        if (atomicInc(&g_barc, NBLK - 1u) == NBLK - 1u) {
            g_barg = old + 1u;                        // release (counter auto-wrapped)
        } else {
            while (g_barg == old) __nanosleep(32);    // read-only spin
        }
        __threadfence();
    }
    __syncthreads();
}

// ---------------- GEMM tile bodies (proven 64x64, 4x4, LDS.128) ----------------
__device__ __forceinline__ void gemm_xw_tile(SMem& sm, const float* __restrict__ X, int ldx,
                                             int K, const float* __restrict__ W,
                                             int col, int row, int g) {
    int tid = threadIdx.x, tx = tid & 15, ty = tid >> 4;
    int colBase = col * 64, rowBase = row * 64;
    float acc[4][4] = {};
    for (int k0 = 0; k0 < K; k0 += 16) {
        __syncthreads();
#pragma unroll
        for (int l = 0; l < 4; l++) {
            int idx = tid + l * 256;
            int m = idx >> 4, kk = idx & 15;
            sm.g.As[kk][m] = X[(size_t)(rowBase + m) * ldx + k0 + kk];
            sm.g.Bs[kk][m] = W[(size_t)(k0 + kk) * NHF + colBase + m];
        }
        __syncthreads();
#pragma unroll
        for (int kk = 0; kk < 16; kk++) {
            float4 a4 = *(const float4*)&sm.g.As[kk][ty * 4];
            float4 b4 = *(const float4*)&sm.g.Bs[kk][tx * 4];
            float av[4] = { a4.x, a4.y, a4.z, a4.w };
            float bv[4] = { b4.x, b4.y, b4.z, b4.w };
#pragma unroll
            for (int i = 0; i < 4; i++)
#pragma unroll
                for (int j = 0; j < 4; j++) acc[i][j] += av[i] * bv[j];
        }
    }
#pragma unroll
    for (int i = 0; i < 4; i++)
#pragma unroll
        for (int j = 0; j < 4; j++)
            g_xw[g][(size_t)(rowBase + ty * 4 + i) * NHF + colBase + tx * 4 + j] = acc[i][j];
}

__device__ __forceinline__ void gates_tile(SMem& sm, int g, int col, int row,
                                           const float* __restrict__ Wih) {
    int tid = threadIdx.x, tx = tid & 15, ty = tid >> 4;
    int colBase = col * 64, rowBase = row * 64;
    const float* A = g_rb[g];
    const float* B = Wih + D6;
    float acc[4][4] = {};
    for (int k0 = 0; k0 < D6; k0 += 16) {
        __syncthreads();
#pragma unroll
        for (int l = 0; l < 4; l++) {
            int idx = tid + l * 256;
            int m = idx >> 4, kk = idx & 15;
            sm.g.As[kk][m] = A[(size_t)(rowBase + m) * D6 + k0 + kk];
            sm.g.Bs[kk][m] = B[(size_t)(colBase + m) * D12 + k0 + kk];
        }
        __syncthreads();
#pragma unroll
        for (int kk = 0; kk < 16; kk++) {
            float4 a4 = *(const float4*)&sm.g.As[kk][ty * 4];
            float4 b4 = *(const float4*)&sm.g.Bs[kk][tx * 4];
            float av[4] = { a4.x, a4.y, a4.z, a4.w };
            float bv[4] = { b4.x, b4.y, b4.z, b4.w };
#pragma unroll
            for (int i = 0; i < 4; i++)
#pragma unroll
                for (int j = 0; j < 4; j++) acc[i][j] += av[i] * bv[j];
        }
    }
#pragma unroll
    for (int i = 0; i < 4; i++) {
        int r = rowBase + ty * 4 + i;
#pragma unroll
        for (int j = 0; j < 4; j++) {
            int c = colBase + tx * 4 + j;
            g_gates[g][(size_t)r * G4 + c] = acc[i][j] + g_cvec[c];
        }
    }
}

__device__ __forceinline__ void mlp1_tile(SMem& sm, int col, int row, int kz,
                                          const float* __restrict__ Wp1) {
    int tid = threadIdx.x, tx = tid & 15, ty = tid >> 4;
    int colBase = col * 64, rowBase = row * 64, kBase = kz * 128;
    float acc[4][4] = {};
    for (int k0 = 0; k0 < 128; k0 += 16) {
        __syncthreads();
#pragma unroll
        for (int l = 0; l < 4; l++) {
            int idx = tid + l * 256;
            int m = idx >> 4, kk = idx & 15;
            sm.g.As[kk][m] = g_z[(size_t)(rowBase + m) * G4 + kBase + k0 + kk];
            sm.g.Bs[kk][m] = Wp1[(size_t)(colBase + m) * G4 + kBase + k0 + kk];
        }
        __syncthreads();
#pragma unroll
        for (int kk = 0; kk < 16; kk++) {
            float4 a4 = *(const float4*)&sm.g.As[kk][ty * 4];
            float4 b4 = *(const float4*)&sm.g.Bs[kk][tx * 4];
            float av[4] = { a4.x, a4.y, a4.z, a4.w };
            float bv[4] = { b4.x, b4.y, b4.z, b4.w };
#pragma unroll
            for (int i = 0; i < 4; i++)
#pragma unroll
                for (int j = 0; j < 4; j++) acc[i][j] += av[i] * bv[j];
        }
    }
#pragma unroll
    for (int i = 0; i < 4; i++)
#pragma unroll
        for (int j = 0; j < 4; j++)
            atomicAdd(&g_z1pre[(size_t)(rowBase + ty * 4 + i) * 256 + colBase + tx * 4 + j],
                      acc[i][j]);
}

// ---------------- gather stage (warp-per-node float4; L2 norm fused on last layer) ----------------
template<bool FUSE_L2>
__device__ __forceinline__ void stage_gather(int off, const float* __restrict__ bias) {
    int lane = threadIdx.x & 31, w = threadIdx.x >> 5;
    for (int t = blockIdx.x * 8 + w; t < 2 * NN; t += NBLK * 8) {
        int g = t >> 13, n = t & (NN - 1);
        const float4* xw4 = (const float4*)g_xw[g];
        float di = g_dinv[g][n];
        float sn = di * di;
        float4 bb = ((const float4*)bias)[lane];
        float4 sv = xw4[(size_t)n * 32 + lane];
        float ax = bb.x + sn * sv.x, ay = bb.y + sn * sv.y;
        float az = bb.z + sn * sv.z, aw = bb.w + sn * sv.w;
        int e0 = g_rowptr[g][n], e1 = g_rowptr[g][n + 1];
        const int* __restrict__ csrc = g_csrc[g];
        const float* __restrict__ cnrm = g_cnrm[g];
        for (int e = e0; e < e1; e++) {
            int s = csrc[e];
            float nm = cnrm[e];
            float4 v = xw4[(size_t)s * 32 + lane];
            ax += nm * v.x; ay += nm * v.y; az += nm * v.z; aw += nm * v.w;
        }
        ax = (ax >= 0.f) ? ax : 0.2f * ax;
        ay = (ay >= 0.f) ? ay : 0.2f * ay;
        az = (az >= 0.f) ? az : 0.2f * az;
        aw = (aw >= 0.f) ? aw : 0.2f * aw;
        if (!FUSE_L2) {
            float4* o = (float4*)(g_h[g] + (size_t)n * H3 + off);
            o[lane] = make_float4(ax, ay, az, aw);
        } else {
            const float4* hrow = (const float4*)(g_h[g] + (size_t)n * H3);
            float4 v0 = hrow[lane];
            float4 v1 = hrow[lane + 32];
            float ss = v0.x * v0.x + v0.y * v0.y + v0.z * v0.z + v0.w * v0.w
                     + v1.x * v1.x + v1.y * v1.y + v1.z * v1.z + v1.w * v1.w
                     + ax * ax + ay * ay + az * az + aw * aw;
            ss = wredsum(ss);
            float inv = 1.f / fmaxf(sqrtf(ss), 1e-12f);
            float4* xr = (float4*)(g_x[g] + (size_t)n * D6);
            xr[lane]      = make_float4(v0.x * inv, v0.y * inv, v0.z * inv, v0.w * inv);
            xr[lane + 32] = make_float4(v1.x * inv, v1.y * inv, v1.z * inv, v1.w * inv);
            xr[lane + 64] = make_float4(ax * inv, ay * inv, az * inv, aw * inv);
        }
    }
}

// ---------------- attention core ----------------
__device__ __forceinline__ void attn_core(SMem& sm, int g, int b, float* rout) {
    int tid = threadIdx.x, lane = tid & 31, w = tid >> 5;
    int s = g_starts[g][b], e = g_starts[g][b + 1], cnt = e - s;
    if (cnt <= 0) {
        for (int j = tid; j < D6; j += NTHR) rout[j] = 0.f;
        return;
    }
    const float* x = g_x[g];
    for (int t = w; t < cnt; t += 8) {
        const float* xr = x + (size_t)(s + t) * D6;
        float p = 0.f;
#pragma unroll
        for (int q = 0; q < 24; q++) p += xr[lane + 32 * q] * sm.a.hq[lane + 32 * q];
        p = wredsum(p);
        if (lane == 0) sm.a.sc[t] = p;
    }
    __syncthreads();
    float lm = -3.4e38f;
    for (int t = tid; t < cnt; t += NTHR) lm = fmaxf(lm, sm.a.sc[t]);
    sm.a.red[tid] = lm; __syncthreads();
    for (int o = 128; o > 0; o >>= 1) { if (tid < o) sm.a.red[tid] = fmaxf(sm.a.red[tid], sm.a.red[tid + o]); __syncthreads(); }
    float m = sm.a.red[0]; __syncthreads();
    float ls = 0.f;
    for (int t = tid; t < cnt; t += NTHR) { float ev = expf(sm.a.sc[t] - m); sm.a.sc[t] = ev; ls += ev; }
    sm.a.red[tid] = ls; __syncthreads();
    for (int o = 128; o > 0; o >>= 1) { if (tid < o) sm.a.red[tid] += sm.a.red[tid + o]; __syncthreads(); }
    float inv = 1.f / sm.a.red[0]; __syncthreads();
    float a0 = 0.f, a1 = 0.f, a2 = 0.f;
    for (int t = 0; t < cnt; t++) {
        float wv = sm.a.sc[t];
        const float* xr = x + (size_t)(s + t) * D6;
        a0 += wv * xr[tid];
        a1 += wv * xr[tid + 256];
        a2 += wv * xr[tid + 512];
    }
    rout[tid] = a0 * inv;
    rout[tid + 256] = a1 * inv;
    rout[tid + 512] = a2 * inv;
}

// ---------------- the mega kernel ----------------
__global__ void __launch_bounds__(NTHR, 4) k_mega(
    const float* __restrict__ f1, const float* __restrict__ f2,
    const float* __restrict__ ea1, const float* __restrict__ ea2,
    const float* __restrict__ W0, const float* __restrict__ bW0,
    const float* __restrict__ W1, const float* __restrict__ bW1,
    const float* __restrict__ W2, const float* __restrict__ bW2,
    const float* __restrict__ Wih, const float* __restrict__ bih,
    const float* __restrict__ Whh, const float* __restrict__ bhh,
    const float* __restrict__ Wp1, const float* __restrict__ bp1,
    const float* __restrict__ Wp2, const float* __restrict__ bp2,
    const float* __restrict__ Wp3, const float* __restrict__ bp3,
    const int* __restrict__ ei1, const int* __restrict__ ei2,
    const int* __restrict__ b1, const int* __restrict__ b2,
    float* __restrict__ out)
{
    __shared__ SMem sm;
    __shared__ int s_wsum[8];
    int tid = threadIdx.x, lane = tid & 31, w = tid >> 5;
    int bid = blockIdx.x;

    // ===== S0: zero cnt/deg + zero z1pre + cvec =====
    for (int i = bid * NTHR + tid; i < 2 * NN; i += NBLK * NTHR) {
        int g = i >> 13, n = i & (NN - 1);
        g_cnt[g][n] = 0;
        g_deg[g][n] = 0.f;
    }
    if (bid < 256) g_z1pre[(size_t)bid * 256 + tid] = 0.f;
    for (int j = tid; j < D6; j += NTHR) {
        float gi = bih[j] + bhh[j];
        float gg = bih[2 * D6 + j] + bhh[2 * D6 + j];
        float go = bih[3 * D6 + j] + bhh[3 * D6 + j];
        float c = sgm(gi) * tanhf(gg);
        sm.a.hq[j] = sgm(go) * tanhf(c);
    }
    __syncthreads();
    {
        int gout = bid * 8 + w;
        if (gout < G4) {
            const float* wi = Wih + (size_t)gout * D12;
            const float* wh = Whh + (size_t)gout * D6;
            float p = 0.f;
#pragma unroll
            for (int t = 0; t < 24; t++) {
                int k = lane + 32 * t;
                p += sm.a.hq[k] * (wi[k] + wh[k]);
            }
            p = wredsum(p);
            if (lane == 0) g_cvec[gout] = bih[gout] + bhh[gout] + p;
        }
    }
    gridbar();

    // ===== S1: count =====
    for (int i = bid * NTHR + tid; i < 2 * NE; i += NBLK * NTHR) {
        int g = i >= NE;
        int e = g ? i - NE : i;
        const int* ei = g ? ei2 : ei1;
        const float* ew = g ? ea2 : ea1;
        int d = ei[NE + e];
        atomicAdd(&g_cnt[g][d], 1);
        atomicAdd(&g_deg[g][d], ew[e]);
    }
    gridbar();

    // ===== S2: scan (blocks 0-1) + dinv/starts + gemm0 =====
    if (bid < 2) {
        int g = bid;
        int b0 = tid * 32;
        int s = 0;
        for (int i = 0; i < 32; i++) s += g_cnt[g][b0 + i];
        int x = s;
#pragma unroll
        for (int o = 1; o < 32; o <<= 1) {
            int y = __shfl_up_sync(0xffffffffu, x, o);
            if (lane >= o) x += y;
        }
        if (lane == 31) s_wsum[w] = x;
        __syncthreads();
        int woff = 0;
        for (int k = 0; k < w; k++) woff += s_wsum[k];
        int run = woff + x - s;
        for (int i = 0; i < 32; i++) {
            int c = g_cnt[g][b0 + i];
            g_rowptr[g][b0 + i] = run;
            g_cursor[g][b0 + i] = run;
            run += c;
        }
        if (tid == NTHR - 1) g_rowptr[g][NN] = run;
        __syncthreads();
    }
    for (int i = bid * NTHR + tid; i < 2 * NN; i += NBLK * NTHR) {
        int g = i >> 13, n = i & (NN - 1);
        g_dinv[g][n] = rsqrtf(g_deg[g][n] + 1.0f);
        const int* batch = g ? b2 : b1;
        int b = batch[n];
        if (n == 0) {
            for (int bb = 0; bb <= b; bb++) g_starts[g][bb] = 0;
        } else {
            int pb = batch[n - 1];
            if (pb != b) for (int bb = pb + 1; bb <= b; bb++) g_starts[g][bb] = n;
        }
        if (n == NN - 1) for (int bb = b + 1; bb <= NB; bb++) g_starts[g][bb] = NN;
    }
    {
        int col = bid & 1, row = (bid >> 1) & 127, g = bid >> 8;
        gemm_xw_tile(sm, g ? f2 : f1, FIN, FIN, W0, col, row, g);
    }
    gridbar();

    // ===== S3: fill CSR =====
    for (int i = bid * NTHR + tid; i < 2 * NE; i += NBLK * NTHR) {
        int g = i >= NE;
        int e = g ? i - NE : i;
        const int* ei = g ? ei2 : ei1;
        const float* ew = g ? ea2 : ea1;
        int s = ei[e], d = ei[NE + e];
        int pos = atomicAdd(&g_cursor[g][d], 1);
        g_csrc[g][pos] = s;
        g_cnrm[g][pos] = g_dinv[g][s] * ew[e] * g_dinv[g][d];
    }
    gridbar();

    // ===== S4: gather layer 0 =====
    stage_gather<false>(0, bW0);
    gridbar();

    // ===== S5: gemm layer 1 =====
    {
        int col = bid & 1, row = (bid >> 1) & 127, g = bid >> 8;
        gemm_xw_tile(sm, g_h[g], H3, NHF, W1, col, row, g);
    }
    gridbar();

    // ===== S6: gather layer 1 =====
    stage_gather<false>(NHF, bW1);
    gridbar();

    // ===== S7: gemm layer 2 =====
    {
        int col = bid & 1, row = (bid >> 1) & 127, g = bid >> 8;
        gemm_xw_tile(sm, g_h[g] + NHF, H3, NHF, W2, col, row, g);
    }
    gridbar();

    // ===== S8: gather layer 2 + fused L2 -> g_x =====
    stage_gather<true>(2 * NHF, bW2);
    gridbar();

    // ===== S9: interaction — 512 blocks: 2 per batch, one per direction =====
    {
        int b = bid & (NB - 1);
        int dir = bid >> 8;                 // 0: graph-0 targets ; 1: graph-1 targets
        int s1 = g_starts[0][b], e1 = g_starts[0][b + 1];
        int s2 = g_starts[1][b], e2 = g_starts[1][b + 1];
        int sA = dir ? s2 : s1, nA = dir ? (e2 - s2) : (e1 - s1);
        int sB = dir ? s1 : s2, nB = dir ? (e1 - s1) : (e2 - s2);
        const float* srcb = g_x[dir];
        const float* oth = g_x[dir ^ 1];
        float* outb = g_x[dir];
        for (int t = w; t < nA; t += 8) {
            int row = sA + t;
            const float* sr = srcb + (size_t)row * D6;
            float svv[12], acc[12];
#pragma unroll
            for (int q = 0; q < 12; q++) { svv[q] = sr[lane + 32 * q]; acc[q] = 0.f; }
            for (int jj = 0; jj < nB; jj++) {
                const float* vr = oth + (size_t)(sB + jj) * D6;
                float vv[12], p = 0.f;
#pragma unroll
                for (int q = 0; q < 12; q++) { vv[q] = vr[lane + 32 * q]; p += svv[q] * vv[q]; }
                p = wredsum(p);
#pragma unroll
                for (int q = 0; q < 12; q++) acc[q] += p * vv[q];
            }
            float* orow = outb + (size_t)row * D6 + H3;
#pragma unroll
            for (int q = 0; q < 12; q++) orow[lane + 32 * q] = acc[q];
        }
    }
    gridbar();

    // ===== S10: attn step 1 -> rb =====
    {
        int g = bid >= NB, b = bid & (NB - 1);
        for (int j = tid; j < D6; j += NTHR) {
            float gi = bih[j] + bhh[j];
            float gg = bih[2 * D6 + j] + bhh[2 * D6 + j];
            float go = bih[3 * D6 + j] + bhh[3 * D6 + j];
            float c = sgm(gi) * tanhf(gg);
            sm.a.hq[j] = sgm(go) * tanhf(c);
        }
        __syncthreads();
        attn_core(sm, g, b, g_rb[g] + (size_t)b * D6);
    }
    gridbar();

    // ===== S11: gates2 GEMM (384 tiles) =====
    for (int t = bid; t < 384; t += NBLK) {
        int col = t % 48, row = (t / 48) & 3, g = t / 192;
        gates_tile(sm, g, col, row, Wih);
    }
    gridbar();

    // ===== S12: attn step 2 (lstm2 + attention) -> z =====
    {
        int g = bid >= NB, b = bid & (NB - 1);
        const float* gt = g_gates[g] + (size_t)b * G4;
        float* zb = g_z + (size_t)b * G4 + (g ? D12 : 0);
        for (int j = tid; j < D6; j += NTHR) {
            float gi1 = bih[j] + bhh[j];
            float gg1 = bih[2 * D6 + j] + bhh[2 * D6 + j];
            float cv = sgm(gi1) * tanhf(gg1);
            float gi = gt[j], gf = gt[D6 + j], gg = gt[2 * D6 + j], go = gt[3 * D6 + j];
            float c = sgm(gf) * cv + sgm(gi) * tanhf(gg);
            float h = sgm(go) * tanhf(c);
            sm.a.hq[j] = h;
            zb[j] = h;
        }
        __syncthreads();
        attn_core(sm, g, b, zb + D6);
    }
    gridbar();

    // ===== S13: mlp1 split-K GEMM (384 tiles, atomic accumulate) =====
    for (int t = bid; t < 384; t += NBLK) {
        int col = t & 3, row = (t >> 2) & 3, kz = t >> 4;
        mlp1_tile(sm, col, row, kz, Wp1);
    }
    gridbar();

    // ===== S14: mlp tail =====
    if (bid < NB) {
        int b = bid;
        float* zs = sm.a.sc;
        float* z2s = sm.a.red;
        zs[tid] = fmaxf(g_z1pre[(size_t)b * 256 + tid] + bp1[tid], 0.f);
        __syncthreads();
#pragma unroll
        for (int oo = 0; oo < 16; oo++) {
            int o = w * 16 + oo;
            const float* wr = Wp2 + (size_t)o * 256;
            float p = 0.f;
#pragma unroll
            for (int k = 0; k < 8; k++) p += zs[lane + 32 * k] * wr[lane + 32 * k];
            p = wredsum(p);
            if (lane == 0) z2s[o] = fmaxf(p + bp2[o], 0.f);
        }
        __syncthreads();
        if (w == 0) {
            float p = 0.f;
#pragma unroll
            for (int k = 0; k < 4; k++) p += z2s[lane + 32 * k] * Wp3[lane + 32 * k];
            p = wredsum(p);
            if (lane == 0) out[b] = 1.f / (1.f + expf(-p - bp3[0]));
        }
    }
}

// ---------------- launch: ONE kernel ----------------
extern "C" void kernel_launch(void* const* d_in, const int* in_sizes, int n_in,
                              void* d_out, int out_size) {
    k_mega<<<NBLK, NTHR>>>(
        (const float*)d_in[0], (const float*)d_in[1],
        (const float*)d_in[2], (const float*)d_in[3],
        (const float*)d_in[4], (const float*)d_in[5],
        (const float*)d_in[6], (const float*)d_in[7],
        (const float*)d_in[8], (const float*)d_in[9],
        (const float*)d_in[10], (const float*)d_in[11],
        (const float*)d_in[12], (const float*)d_in[13],
        (const float*)d_in[14], (const float*)d_in[15],
        (const float*)d_in[16], (const float*)d_in[17],
        (const float*)d_in[18], (const float*)d_in[19],
        (const int*)d_in[20], (const int*)d_in[21],
        (const int*)d_in[22], (const int*)d_in[23],
        (float*)d_out);
}

// round 12
// speedup vs baseline: 1.1749x; 1.0403x over previous
#include <cuda_runtime.h>

#define NN   8192
#define NE   131072
#define NB   256
#define NHF  128
#define FIN  64
#define H3   384
#define D6   768
#define D12  1536
#define G4   3072

// ---------------- scratch ----------------
__device__ __align__(16) float g_h[2][NN * H3];
__device__ __align__(16) float g_x[2][NN * D6];
__device__ __align__(16) float g_xw[2][NN * NHF];
__device__ float g_deg[2][NN];
__device__ int   g_cnt[2][NN];
__device__ int   g_cursor[2][NN];
__device__ int   g_rowptr[2][NN + 1];
__device__ int   g_csrc[2][NE];
__device__ float g_cnrm[2][NE];
__device__ float g_dinv[2][NN];
__device__ int   g_starts[2][NB + 1];
__device__ float g_cvec[G4];
__device__ __align__(16) float g_rb[2][NB * D6];
__device__ __align__(16) float g_gates[2][NB * G4];
__device__ __align__(16) float g_z[NB * G4];
__device__ __align__(16) float g_z1pre[NB * 256];

__device__ __forceinline__ float wredsum(float v) {
#pragma unroll
    for (int o = 16; o; o >>= 1) v += __shfl_xor_sync(0xffffffffu, v, o);
    return v;
}
__device__ __forceinline__ float sgm(float x) { return 1.f / (1.f + expf(-x)); }

// ---------------- CSR build (R8 proven) ----------------
__global__ void k_prep() {
    int i = blockIdx.x * blockDim.x + threadIdx.x;
    if (i < 2 * NN) {
        int g = i >> 13, n = i & (NN - 1);
        g_cnt[g][n] = 0;
        g_deg[g][n] = 0.f;
    }
}
__global__ void k_count(const int* __restrict__ ei1, const float* __restrict__ ew1,
                        const int* __restrict__ ei2, const float* __restrict__ ew2) {
    int g = blockIdx.y;
    const int* ei = g ? ei2 : ei1;
    const float* ew = g ? ew2 : ew1;
    int e = blockIdx.x * blockDim.x + threadIdx.x;
    if (e < NE) {
        int d = ei[NE + e];
        atomicAdd(&g_cnt[g][d], 1);
        atomicAdd(&g_deg[g][d], ew[e]);
    }
}
__global__ void k_scan() {
    __shared__ int wsum[32];
    int g = blockIdx.x;
    int t = threadIdx.x, lane = t & 31, w = t >> 5;
    int base = t * 8;
    int loc[8], s = 0;
#pragma unroll
    for (int i = 0; i < 8; i++) { loc[i] = s; s += g_cnt[g][base + i]; }
    int x = s;
#pragma unroll
    for (int o = 1; o < 32; o <<= 1) {
        int y = __shfl_up_sync(0xffffffffu, x, o);
        if (lane >= o) x += y;
    }
    if (lane == 31) wsum[w] = x;
    __syncthreads();
    if (w == 0) {
        int y = wsum[lane];
#pragma unroll
        for (int o = 1; o < 32; o <<= 1) {
            int z = __shfl_up_sync(0xffffffffu, y, o);
            if (lane >= o) y += z;
        }
        wsum[lane] = y;
    }
    __syncthreads();
    int off = x - s + ((w > 0) ? wsum[w - 1] : 0);
#pragma unroll
    for (int i = 0; i < 8; i++) {
        g_rowptr[g][base + i] = off + loc[i];
        g_cursor[g][base + i] = off + loc[i];
    }
    if (t == 1023) g_rowptr[g][NN] = wsum[31];
}
__global__ void k_startsdinv(const int* __restrict__ b1, const int* __restrict__ b2) {
    int g = blockIdx.y;
    int n = blockIdx.x * blockDim.x + threadIdx.x;
    if (n >= NN) return;
    g_dinv[g][n] = rsqrtf(g_deg[g][n] + 1.0f);
    const int* batch = g ? b2 : b1;
    int b = batch[n];
    if (n == 0) {
        for (int bb = 0; bb <= b; bb++) g_starts[g][bb] = 0;
    } else {
        int pb = batch[n - 1];
        if (pb != b) for (int bb = pb + 1; bb <= b; bb++) g_starts[g][bb] = n;
    }
    if (n == NN - 1) for (int bb = b + 1; bb <= NB; bb++) g_starts[g][bb] = NN;
}
__global__ void k_fill(const int* __restrict__ ei1, const float* __restrict__ ew1,
                       const int* __restrict__ ei2, const float* __restrict__ ew2) {
    int g = blockIdx.y;
    const int* ei = g ? ei2 : ei1;
    const float* ew = g ? ew2 : ew1;
    int e = blockIdx.x * blockDim.x + threadIdx.x;
    if (e >= NE) return;
    int s = ei[e], d = ei[NE + e];
    int pos = atomicAdd(&g_cursor[g][d], 1);
    g_csrc[g][pos] = s;
    g_cnrm[g][pos] = g_dinv[g][s] * ew[e] * g_dinv[g][d];
}

// ---------------- tiled GEMM (R8 proven 64x64, 4x4, LDS.128) ----------------
__global__ void k_gemm_xw(const float* __restrict__ f1, const float* __restrict__ f2,
                          int layer, const float* __restrict__ W) {
    __shared__ float As[16][64];
    __shared__ float Bs[16][68];
    int g = blockIdx.z;
    const float* X;
    int ldx, K;
    if (layer == 0) { X = g ? f2 : f1; ldx = FIN; K = FIN; }
    else            { X = g_h[g] + (layer - 1) * NHF; ldx = H3; K = NHF; }
    int tid = threadIdx.x, tx = tid & 15, ty = tid >> 4;
    int colBase = blockIdx.x * 64, rowBase = blockIdx.y * 64;
    float acc[4][4] = {};
    for (int k0 = 0; k0 < K; k0 += 16) {
#pragma unroll
        for (int l = 0; l < 4; l++) {
            int idx = tid + l * 256;
            int m = idx >> 4, kk = idx & 15;
            As[kk][m] = X[(size_t)(rowBase + m) * ldx + k0 + kk];
            Bs[kk][m] = W[(size_t)(k0 + kk) * NHF + colBase + m];
        }
        __syncthreads();
#pragma unroll
        for (int kk = 0; kk < 16; kk++) {
            float4 a4 = *(const float4*)&As[kk][ty * 4];
            float4 b4 = *(const float4*)&Bs[kk][tx * 4];
            float av[4] = { a4.x, a4.y, a4.z, a4.w };
            float bv[4] = { b4.x, b4.y, b4.z, b4.w };
#pragma unroll
            for (int i = 0; i < 4; i++)
#pragma unroll
                for (int j = 0; j < 4; j++) acc[i][j] += av[i] * bv[j];
        }
        __syncthreads();
    }
#pragma unroll
    for (int i = 0; i < 4; i++)
#pragma unroll
        for (int j = 0; j < 4; j++)
            g_xw[g][(size_t)(rowBase + ty * 4 + i) * NHF + colBase + tx * 4 + j] = acc[i][j];
}

// ---------------- gather (R8 proven warp-per-node float4; L2 norm fused when last) ----------------
template<bool FUSE_L2>
__global__ void k_gather_t(int off, const float* __restrict__ bias) {
    int g = blockIdx.y;
    int n = blockIdx.x * 8 + (threadIdx.x >> 5);
    int lane = threadIdx.x & 31;
    if (n >= NN) return;
    const float4* xw4 = (const float4*)g_xw[g];
    float di = g_dinv[g][n];
    float sn = di * di;
    float4 bb = ((const float4*)bias)[lane];
    float4 sv = xw4[(size_t)n * 32 + lane];
    float ax = bb.x + sn * sv.x, ay = bb.y + sn * sv.y;
    float az = bb.z + sn * sv.z, aw = bb.w + sn * sv.w;
    int e0 = g_rowptr[g][n], e1 = g_rowptr[g][n + 1];
    const int* __restrict__ csrc = g_csrc[g];
    const float* __restrict__ cnrm = g_cnrm[g];
    for (int e = e0; e < e1; e++) {
        int s = csrc[e];
        float nm = cnrm[e];
        float4 v = xw4[(size_t)s * 32 + lane];
        ax += nm * v.x; ay += nm * v.y; az += nm * v.z; aw += nm * v.w;
    }
    ax = (ax >= 0.f) ? ax : 0.2f * ax;
    ay = (ay >= 0.f) ? ay : 0.2f * ay;
    az = (az >= 0.f) ? az : 0.2f * az;
    aw = (aw >= 0.f) ? aw : 0.2f * aw;
    if (!FUSE_L2) {
        float4* o = (float4*)(g_h[g] + (size_t)n * H3 + off);
        o[lane] = make_float4(ax, ay, az, aw);
    } else {
        const float4* hrow = (const float4*)(g_h[g] + (size_t)n * H3);
        float4 v0 = hrow[lane];
        float4 v1 = hrow[lane + 32];
        float ss = v0.x * v0.x + v0.y * v0.y + v0.z * v0.z + v0.w * v0.w
                 + v1.x * v1.x + v1.y * v1.y + v1.z * v1.z + v1.w * v1.w
                 + ax * ax + ay * ay + az * az + aw * aw;
        ss = wredsum(ss);
        float inv = 1.f / fmaxf(sqrtf(ss), 1e-12f);
        float4* xr = (float4*)(g_x[g] + (size_t)n * D6);
        xr[lane]      = make_float4(v0.x * inv, v0.y * inv, v0.z * inv, v0.w * inv);
        xr[lane + 32] = make_float4(v1.x * inv, v1.y * inv, v1.z * inv, v1.w * inv);
        xr[lane + 64] = make_float4(ax * inv, ay * inv, az * inv, aw * inv);
    }
}

// ---------------- interaction (R8 proven: single-pass, 512 thr) ----------------
__global__ void __launch_bounds__(512) k_interact() {
    int b = blockIdx.x;
    int s1 = g_starts[0][b], e1 = g_starts[0][b + 1];
    int s2 = g_starts[1][b], e2 = g_starts[1][b + 1];
    int n1 = e1 - s1, n2 = e2 - s2, tot = n1 + n2;
    int lane = threadIdx.x & 31, w = threadIdx.x >> 5;
    for (int t = w; t < tot; t += 16) {
        const float *src, *oth;
        float* out;
        int row, obase, ocnt;
        if (t < n1) { row = s1 + t;        src = g_x[0]; oth = g_x[1]; obase = s2; ocnt = n2; out = g_x[0]; }
        else        { row = s2 + (t - n1); src = g_x[1]; oth = g_x[0]; obase = s1; ocnt = n1; out = g_x[1]; }
        const float* sr = src + (size_t)row * D6;
        float sv[12], acc[12];
#pragma unroll
        for (int q = 0; q < 12; q++) { sv[q] = sr[lane + 32 * q]; acc[q] = 0.f; }
        for (int jj = 0; jj < ocnt; jj++) {
            const float* vr = oth + (size_t)(obase + jj) * D6;
            float vv[12], p = 0.f;
#pragma unroll
            for (int q = 0; q < 12; q++) { vv[q] = vr[lane + 32 * q]; p += sv[q] * vv[q]; }
            p = wredsum(p);
#pragma unroll
            for (int q = 0; q < 12; q++) acc[q] += p * vv[q];
        }
        float* orow = out + (size_t)row * D6 + H3;
#pragma unroll
        for (int q = 0; q < 12; q++) orow[lane + 32 * q] = acc[q];
    }
}

// ---------------- cvec + z1pre zero (R8 proven) ----------------
__global__ void k_cvec(const float* __restrict__ Wih, const float* __restrict__ Whh,
                       const float* __restrict__ bih, const float* __restrict__ bhh) {
    __shared__ float shv[D6];
    int tid = threadIdx.x, lane = tid & 31, w = tid >> 5;
    for (int j = tid; j < D6; j += 256) {
        float gi = bih[j] + bhh[j];
        float gg = bih[2 * D6 + j] + bhh[2 * D6 + j];
        float go = bih[3 * D6 + j] + bhh[3 * D6 + j];
        float c = sgm(gi) * tanhf(gg);
        shv[j] = sgm(go) * tanhf(c);
    }
    if (blockIdx.x < 256) g_z1pre[blockIdx.x * 256 + tid] = 0.f;
    __syncthreads();
    int gout = blockIdx.x * 8 + w;
    const float* wi = Wih + (size_t)gout * D12;
    const float* wh = Whh + (size_t)gout * D6;
    float p = 0.f;
#pragma unroll
    for (int t = 0; t < 24; t++) {
        int k = lane + 32 * t;
        p += shv[k] * (wi[k] + wh[k]);
    }
    p = wredsum(p);
    if (lane == 0) g_cvec[gout] = bih[gout] + bhh[gout] + p;
}

// ---------------- ONLINE-SOFTMAX attention core: rows read once ----------------
__device__ __forceinline__ void attn_online(const float* __restrict__ hq_s, int g, int b,
                                            float* rout,
                                            float* sacc, float* sM, float* sS) {
    int tid = threadIdx.x, lane = tid & 31, w = tid >> 5;
    int s = g_starts[g][b], e = g_starts[g][b + 1], cnt = e - s;
    if (cnt <= 0) {
        for (int j = tid; j < D6; j += 256) rout[j] = 0.f;
        return;
    }
    const float* x = g_x[g];
    float M = -3.4e38f, S = 0.f;
    float acc[24];
#pragma unroll
    for (int q = 0; q < 24; q++) acc[q] = 0.f;
    for (int t = w; t < cnt; t += 8) {
        const float* xr = x + (size_t)(s + t) * D6;
        float xv[24], p = 0.f;
#pragma unroll
        for (int q = 0; q < 24; q++) { xv[q] = xr[lane + 32 * q]; p += xv[q] * hq_s[lane + 32 * q]; }
        p = wredsum(p);
        if (p > M) {
            float r = expf(M - p);
            S *= r;
#pragma unroll
            for (int q = 0; q < 24; q++) acc[q] *= r;
            M = p;
        }
        float ev = expf(p - M);
        S += ev;
#pragma unroll
        for (int q = 0; q < 24; q++) acc[q] += ev * xv[q];
    }
    if (lane == 0) { sM[w] = M; sS[w] = S; }
    for (int j = tid; j < D6; j += 256) sacc[j] = 0.f;
    __syncthreads();
    float Mg = sM[0];
#pragma unroll
    for (int i = 1; i < 8; i++) Mg = fmaxf(Mg, sM[i]);
    float scale = expf(M - Mg);
    for (int r = 0; r < 8; r++) {
        if (w == r) {
#pragma unroll
            for (int q = 0; q < 24; q++) sacc[lane + 32 * q] += scale * acc[q];
        }
        __syncthreads();
    }
    float Sg = 0.f;
#pragma unroll
    for (int i = 0; i < 8; i++) Sg += sS[i] * expf(sM[i] - Mg);
    float inv = 1.f / Sg;
    rout[tid] = sacc[tid] * inv;
    rout[tid + 256] = sacc[tid + 256] * inv;
    rout[tid + 512] = sacc[tid + 512] * inv;
}

__global__ void k_attn1(const float* __restrict__ bih, const float* __restrict__ bhh) {
    __shared__ float hq[D6];
    __shared__ float sacc[D6];
    __shared__ float sM[8], sS[8];
    int g = blockIdx.y, b = blockIdx.x;
    int tid = threadIdx.x;
    for (int j = tid; j < D6; j += 256) {
        float gi = bih[j] + bhh[j];
        float gg = bih[2 * D6 + j] + bhh[2 * D6 + j];
        float go = bih[3 * D6 + j] + bhh[3 * D6 + j];
        float c = sgm(gi) * tanhf(gg);
        hq[j] = sgm(go) * tanhf(c);
    }
    __syncthreads();
    attn_online(hq, g, b, g_rb[g] + (size_t)b * D6, sacc, sM, sS);
}

// gates2 (R8 proven)
__global__ void k_gates2(const float* __restrict__ Wih) {
    __shared__ float As[16][64];
    __shared__ float Bs[16][68];
    int g = blockIdx.z;
    int tid = threadIdx.x, tx = tid & 15, ty = tid >> 4;
    int colBase = blockIdx.x * 64, rowBase = blockIdx.y * 64;
    const float* A = g_rb[g];
    const float* B = Wih + D6;
    float acc[4][4] = {};
    for (int k0 = 0; k0 < D6; k0 += 16) {
#pragma unroll
        for (int l = 0; l < 4; l++) {
            int idx = tid + l * 256;
            int m = idx >> 4, kk = idx & 15;
            As[kk][m] = A[(size_t)(rowBase + m) * D6 + k0 + kk];
            Bs[kk][m] = B[(size_t)(colBase + m) * D12 + k0 + kk];
        }
        __syncthreads();
#pragma unroll
        for (int kk = 0; kk < 16; kk++) {
            float4 a4 = *(const float4*)&As[kk][ty * 4];
            float4 b4 = *(const float4*)&Bs[kk][tx * 4];
            float av[4] = { a4.x, a4.y, a4.z, a4.w };
            float bv[4] = { b4.x, b4.y, b4.z, b4.w };
#pragma unroll
            for (int i = 0; i < 4; i++)
#pragma unroll
                for (int j = 0; j < 4; j++) acc[i][j] += av[i] * bv[j];
        }
        __syncthreads();
    }
#pragma unroll
    for (int i = 0; i < 4; i++) {
        int row = rowBase + ty * 4 + i;
#pragma unroll
        for (int j = 0; j < 4; j++) {
            int col = colBase + tx * 4 + j;
            g_gates[g][(size_t)row * G4 + col] = acc[i][j] + g_cvec[col];
        }
    }
}

__global__ void k_attn2(const float* __restrict__ bih, const float* __restrict__ bhh) {
    __shared__ float hq[D6];
    __shared__ float sacc[D6];
    __shared__ float sM[8], sS[8];
    int g = blockIdx.y, b = blockIdx.x;
    int tid = threadIdx.x;
    const float* gt = g_gates[g] + (size_t)b * G4;
    float* zb = g_z + (size_t)b * G4 + (g ? D12 : 0);
    for (int j = tid; j < D6; j += 256) {
        float gi1 = bih[j] + bhh[j];
        float gg1 = bih[2 * D6 + j] + bhh[2 * D6 + j];
        float cv = sgm(gi1) * tanhf(gg1);
        float gi = gt[j], gf = gt[D6 + j], gg = gt[2 * D6 + j], go = gt[3 * D6 + j];
        float c = sgm(gf) * cv + sgm(gi) * tanhf(gg);
        float h = sgm(go) * tanhf(c);
        hq[j] = h;
        zb[j] = h;
    }
    __syncthreads();
    attn_online(hq, g, b, zb + D6, sacc, sM, sS);
}

// ---------------- MLP head ----------------
__global__ void k_mlp1_gemm(const float* __restrict__ Wp1) {
    __shared__ float As[16][64];
    __shared__ float Bs[16][68];
    int tid = threadIdx.x, tx = tid & 15, ty = tid >> 4;
    int colBase = blockIdx.x * 64, rowBase = blockIdx.y * 64;
    int kBase = blockIdx.z * 128;
    float acc[4][4] = {};
    for (int k0 = 0; k0 < 128; k0 += 16) {
#pragma unroll
        for (int l = 0; l < 4; l++) {
            int idx = tid + l * 256;
            int m = idx >> 4, kk = idx & 15;
            As[kk][m] = g_z[(size_t)(rowBase + m) * G4 + kBase + k0 + kk];
            Bs[kk][m] = Wp1[(size_t)(colBase + m) * G4 + kBase + k0 + kk];
        }
        __syncthreads();
#pragma unroll
        for (int kk = 0; kk < 16; kk++) {
            float4 a4 = *(const float4*)&As[kk][ty * 4];
            float4 b4 = *(const float4*)&Bs[kk][tx * 4];
            float av[4] = { a4.x, a4.y, a4.z, a4.w };
            float bv[4] = { b4.x, b4.y, b4.z, b4.w };
#pragma unroll
            for (int i = 0; i < 4; i++)
#pragma unroll
                for (int j = 0; j < 4; j++) acc[i][j] += av[i] * bv[j];
        }
        __syncthreads();
    }
#pragma unroll
    for (int i = 0; i < 4; i++)
#pragma unroll
        for (int j = 0; j < 4; j++)
            atomicAdd(&g_z1pre[(size_t)(rowBase + ty * 4 + i) * 256 + colBase + tx * 4 + j],
                      acc[i][j]);
}
__global__ void k_mlp2f(const float* __restrict__ bp1,
                        const float* __restrict__ Wp2, const float* __restrict__ bp2,
                        const float* __restrict__ Wp3, const float* __restrict__ bp3,
                        float* __restrict__ out) {
    __shared__ float zs[256];
    __shared__ float z2s[128];
    int b = blockIdx.x, tid = threadIdx.x, lane = tid & 31, w = tid >> 5;
    zs[tid] = fmaxf(g_z1pre[(size_t)b * 256 + tid] + bp1[tid], 0.f);
    __syncthreads();
#pragma unroll
    for (int oo = 0; oo < 16; oo++) {
        int o = w * 16 + oo;
        const float* wr = Wp2 + (size_t)o * 256;
        float p = 0.f;
#pragma unroll
        for (int k = 0; k < 8; k++) p += zs[lane + 32 * k] * wr[lane + 32 * k];
        p = wredsum(p);
        if (lane == 0) z2s[o] = fmaxf(p + bp2[o], 0.f);
    }
    __syncthreads();
    if (w == 0) {
        float p = 0.f;
#pragma unroll
        for (int k = 0; k < 4; k++) p += z2s[lane + 32 * k] * Wp3[lane + 32 * k];
        p = wredsum(p);
        if (lane == 0) out[b] = 1.f / (1.f + expf(-p - bp3[0]));
    }
}

// ---------------- launch sequence ----------------
extern "C" void kernel_launch(void* const* d_in, const int* in_sizes, int n_in,
                              void* d_out, int out_size) {
    const float* f1 = (const float*)d_in[0];
    const float* f2 = (const float*)d_in[1];
    const float* ea1 = (const float*)d_in[2];
    const float* ea2 = (const float*)d_in[3];
    const float* W[3]  = { (const float*)d_in[4], (const float*)d_in[6], (const float*)d_in[8] };
    const float* bW[3] = { (const float*)d_in[5], (const float*)d_in[7], (const float*)d_in[9] };
    const float* Wih = (const float*)d_in[10];
    const float* bih = (const float*)d_in[11];
    const float* Whh = (const float*)d_in[12];
    const float* bhh = (const float*)d_in[13];
    const float* Wp1 = (const float*)d_in[14];
    const float* bp1 = (const float*)d_in[15];
    const float* Wp2 = (const float*)d_in[16];
    const float* bp2 = (const float*)d_in[17];
    const float* Wp3 = (const float*)d_in[18];
    const float* bp3 = (const float*)d_in[19];
    const int* ei1 = (const int*)d_in[20];
    const int* ei2 = (const int*)d_in[21];
    const int* b1 = (const int*)d_in[22];
    const int* b2 = (const int*)d_in[23];
    float* out = (float*)d_out;

    static cudaStream_t s1 = (cudaStream_t)0;
    static cudaEvent_t evA, evB;
    static bool inited = false;
    if (!inited) {
        cudaStreamCreateWithFlags(&s1, cudaStreamNonBlocking);
        cudaEventCreateWithFlags(&evA, cudaEventDisableTiming);
        cudaEventCreateWithFlags(&evB, cudaEventDisableTiming);
        inited = true;
    }
    cudaStream_t s0 = (cudaStream_t)0;
    const int T = 256;

    // side stream: CSR build overlapped with cvec + layer-0 GEMM on s0
    cudaEventRecord(evA, s0);
    cudaStreamWaitEvent(s1, evA, 0);
    k_prep<<<2 * NN / T, T, 0, s1>>>();
    k_count<<<dim3(NE / T, 2), T, 0, s1>>>(ei1, ea1, ei2, ea2);
    k_scan<<<2, 1024, 0, s1>>>();
    k_startsdinv<<<dim3(NN / T, 2), T, 0, s1>>>(b1, b2);
    k_fill<<<dim3(NE / T, 2), T, 0, s1>>>(ei1, ea1, ei2, ea2);
    cudaEventRecord(evB, s1);

    k_cvec<<<G4 / 8, T, 0, s0>>>(Wih, Whh, bih, bhh);
    k_gemm_xw<<<dim3(2, NN / 64, 2), T, 0, s0>>>(f1, f2, 0, W[0]);

    cudaStreamWaitEvent(s0, evB, 0);
    k_gather_t<false><<<dim3(NN / 8, 2), T, 0, s0>>>(0, bW[0]);
    k_gemm_xw<<<dim3(2, NN / 64, 2), T, 0, s0>>>(f1, f2, 1, W[1]);
    k_gather_t<false><<<dim3(NN / 8, 2), T, 0, s0>>>(NHF, bW[1]);
    k_gemm_xw<<<dim3(2, NN / 64, 2), T, 0, s0>>>(f1, f2, 2, W[2]);
    k_gather_t<true><<<dim3(NN / 8, 2), T, 0, s0>>>(2 * NHF, bW[2]);   // + fused L2 -> g_x
    k_interact<<<NB, 512, 0, s0>>>();

    k_attn1<<<dim3(NB, 2), T, 0, s0>>>(bih, bhh);
    k_gates2<<<dim3(G4 / 64, NB / 64, 2), T, 0, s0>>>(Wih);
    k_attn2<<<dim3(NB, 2), T, 0, s0>>>(bih, bhh);

    k_mlp1_gemm<<<dim3(4, 4, 24), T, 0, s0>>>(Wp1);
    k_mlp2f<<<NB, T, 0, s0>>>(bp1, Wp2, bp2, Wp3, bp3, out);
}